// round 12
// baseline (speedup 1.0000x reference)
#include <cuda_runtime.h>

#define IMG 256
#define TW 64
#define TH 16
#define PR (TH + 6)   // 22 quartet-plane rows

typedef unsigned long long u64;

// ---- packed f32x2 helpers (sm_103a FFMA2 path, PTX-only) ----
__device__ __forceinline__ u64 pk2(float lo, float hi) {
    u64 r; asm("mov.b64 %0, {%1,%2};" : "=l"(r) : "f"(lo), "f"(hi)); return r;
}
__device__ __forceinline__ void upk2(float& lo, float& hi, u64 p) {
    asm("mov.b64 {%0,%1}, %2;" : "=f"(lo), "=f"(hi) : "l"(p));
}
__device__ __forceinline__ u64 f2fma(u64 a, u64 b, u64 c) {
    u64 d; asm("fma.rn.f32x2 %0,%1,%2,%3;" : "=l"(d) : "l"(a), "l"(b), "l"(c)); return d;
}
__device__ __forceinline__ u64 f2mul(u64 a, u64 b) {
    u64 d; asm("mul.rn.f32x2 %0,%1,%2;" : "=l"(d) : "l"(a), "l"(b)); return d;
}
__device__ __forceinline__ u64 f2add(u64 a, u64 b) {
    u64 d; asm("add.rn.f32x2 %0,%1,%2;" : "=l"(d) : "l"(a), "l"(b)); return d;
}
__device__ __forceinline__ float ex2f(float x) {
    float r; asm("ex2.approx.f32 %0, %1;" : "=f"(r) : "f"(x)); return r;
}
__device__ __forceinline__ float rcpf(float x) {
    float r; asm("rcp.approx.f32 %0, %1;" : "=f"(r) : "f"(x)); return r;
}

__device__ __forceinline__ int reflect(int v) {
    v = (v < 0) ? -v : v;
    return (v > IMG - 1) ? 2 * (IMG - 1) - v : v;
}

__global__ __launch_bounds__(256, 5)
void AdaptiveGaussianFilter_66675072303489_kernel(
    const float* __restrict__ x,
    const float* __restrict__ sigma,
    float* __restrict__ out)
{
    // Planar quartet planes: m=w0, a=w-1+w+1, b=w-2+w+2, c=w-3+w+3 (22.5 KB)
    __shared__ __align__(16) float qm[PR][TW];
    __shared__ __align__(16) float qa[PR][TW];
    __shared__ __align__(16) float qb[PR][TW];
    __shared__ __align__(16) float qc[PR][TW];

    const int ch = blockIdx.z;
    const int x0 = blockIdx.x * TW;
    const int y0 = blockIdx.y * TH;

    const float* xc = x     + (size_t)ch * IMG * IMG;
    const float* sc = sigma + (size_t)ch * IMG * IMG;
    float*       oc = out   + (size_t)ch * IMG * IMG;

    const int tx  = threadIdx.x;
    const int ty  = threadIdx.y;
    const int tid = ty * 32 + tx;

    const int c2  = tx << 1;                 // column 0..62
    const int ly0 = ty << 1;                 // output row 0..14 (2 rows/thread)

    // Preload both sigma pairs (latency hides under pass-1)
    const float* sp = sc + (y0 + ly0) * IMG + x0 + c2;
    u64 sg[2];
    sg[0] = *(const u64*)(sp);
    sg[1] = *(const u64*)(sp + IMG);

    // ---- Pass 1: build quartet planes straight from gmem (R9-style strips) ----
    const bool interior = (blockIdx.x != 0) & (blockIdx.x != 3) &
                          (blockIdx.y != 0) & (blockIdx.y != 15);
    #pragma unroll
    for (int it = 0; it < 2; it++) {
        int idx = tid + it * 256;
        if (idx < PR * 16) {                 // 22 rows x 16 strips of 4 cols = 352
            int r  = idx >> 4;
            int c0 = (idx & 15) << 2;
            float w[10];                     // x[x0+c0-3 .. x0+c0+6]
            if (interior) {
                const float* src = xc + (y0 + r - 3) * IMG + (x0 + c0 - 3);
                #pragma unroll
                for (int i = 0; i < 10; i++) w[i] = src[i];
            } else {
                const float* srow = xc + reflect(y0 + r - 3) * IMG;
                #pragma unroll
                for (int i = 0; i < 10; i++) w[i] = srow[reflect(x0 + c0 - 3 + i)];
            }
            *(float4*)&qm[r][c0] = make_float4(w[3], w[4], w[5], w[6]);
            *(float4*)&qa[r][c0] = make_float4(w[2]+w[4], w[3]+w[5], w[4]+w[6], w[5]+w[7]);
            *(float4*)&qb[r][c0] = make_float4(w[1]+w[5], w[2]+w[6], w[3]+w[7], w[4]+w[8]);
            *(float4*)&qc[r][c0] = make_float4(w[0]+w[6], w[1]+w[7], w[2]+w[8], w[3]+w[9]);
        }
    }

    // ---- Exp chains for both output rows BEFORE the barrier (MUFU hidden) ----
    const u64 NHL = pk2(-0.72134752f, -0.72134752f);   // -0.5*log2(e)
    u64 t[2], t4[2], t9[2];
    #pragma unroll
    for (int k = 0; k < 2; k++) {
        u64 z = f2mul(sg[k], sg[k]);
        z = f2mul(z, NHL);
        float zl, zh; upk2(zl, zh, z);
        t[k]  = pk2(ex2f(zl), ex2f(zh));
        u64 t2 = f2mul(t[k], t[k]);
        t4[k] = f2mul(t2, t2);
        t9[k] = f2mul(f2mul(t4[k], t4[k]), t[k]);
    }
    __syncthreads();

    // ---- Pass 2: stream 8 window rows; 2 packed accumulators ----
    u64 acc[2];
    #pragma unroll
    for (int w = -3; w <= 4; w++) {
        const int prow = ly0 + w + 3;        // 0..21
        const u64 qm_ = *(const u64*)&qm[prow][c2];
        const u64 qa_ = *(const u64*)&qa[prow][c2];
        const u64 qb_ = *(const u64*)&qb[prow][c2];
        const u64 qc_ = *(const u64*)&qc[prow][c2];
        #pragma unroll
        for (int k = 0; k < 2; k++) {
            const int d = (w > k) ? (w - k) : (k - w);
            if (d > 3) continue;
            u64 h = f2fma(t[k],  qa_, qm_);
            h     = f2fma(t4[k], qb_, h);
            h     = f2fma(t9[k], qc_, h);
            if (w == k - 3)     acc[k] = f2mul(t9[k], h);     // first contribution
            else if (d == 3)    acc[k] = f2fma(t9[k], h, acc[k]);
            else if (d == 2)    acc[k] = f2fma(t4[k], h, acc[k]);
            else if (d == 1)    acc[k] = f2fma(t[k],  h, acc[k]);
            else                acc[k] = f2add(acc[k], h);
        }
    }

    // ---- Epilogue: normalize and store ----
    const u64 TWO2 = pk2(2.0f, 2.0f);
    const u64 ONE2 = pk2(1.0f, 1.0f);
    float* op = oc + (y0 + ly0) * IMG + x0 + c2;
    #pragma unroll
    for (int k = 0; k < 2; k++) {
        u64 S  = f2fma(TWO2, f2add(f2add(t[k], t4[k]), t9[k]), ONE2);
        u64 SS = f2mul(S, S);
        float sl, sh; upk2(sl, sh, SS);
        float al, ah; upk2(al, ah, acc[k]);
        *(u64*)(op + k * IMG) = pk2(al * rcpf(sl), ah * rcpf(sh));
    }
}

extern "C" void kernel_launch(void* const* d_in, const int* in_sizes, int n_in,
                              void* d_out, int out_size)
{
    const float* x     = (const float*)d_in[0];
    const float* sigma = (const float*)d_in[1];
    float*       out   = (float*)d_out;

    dim3 block(32, 8, 1);
    dim3 grid(IMG / TW, IMG / TH, 16 * 3);   // 4 x 16 x 48 = 3072
    AdaptiveGaussianFilter_66675072303489_kernel<<<grid, block>>>(x, sigma, out);
}

// round 13
// speedup vs baseline: 1.0943x; 1.0943x over previous
#include <cuda_runtime.h>

#define IMG 256
#define TW 64
#define TH 32
#define PR (TH + 6)   // 38 quartet-plane rows

typedef unsigned long long u64;

// ---- packed f32x2 helpers (sm_103a FFMA2 path, PTX-only) ----
__device__ __forceinline__ u64 pk2(float lo, float hi) {
    u64 r; asm("mov.b64 %0, {%1,%2};" : "=l"(r) : "f"(lo), "f"(hi)); return r;
}
__device__ __forceinline__ void upk2(float& lo, float& hi, u64 p) {
    asm("mov.b64 {%0,%1}, %2;" : "=f"(lo), "=f"(hi) : "l"(p));
}
__device__ __forceinline__ u64 f2fma(u64 a, u64 b, u64 c) {
    u64 d; asm("fma.rn.f32x2 %0,%1,%2,%3;" : "=l"(d) : "l"(a), "l"(b), "l"(c)); return d;
}
__device__ __forceinline__ u64 f2mul(u64 a, u64 b) {
    u64 d; asm("mul.rn.f32x2 %0,%1,%2;" : "=l"(d) : "l"(a), "l"(b)); return d;
}
__device__ __forceinline__ u64 f2add(u64 a, u64 b) {
    u64 d; asm("add.rn.f32x2 %0,%1,%2;" : "=l"(d) : "l"(a), "l"(b)); return d;
}
__device__ __forceinline__ float ex2f(float x) {
    float r; asm("ex2.approx.f32 %0, %1;" : "=f"(r) : "f"(x)); return r;
}
__device__ __forceinline__ float rcpf(float x) {
    float r; asm("rcp.approx.f32 %0, %1;" : "=f"(r) : "f"(x)); return r;
}

__device__ __forceinline__ int reflect(int v) {
    v = (v < 0) ? -v : v;
    return (v > IMG - 1) ? 2 * (IMG - 1) - v : v;
}

__global__ __launch_bounds__(256, 4)
void AdaptiveGaussianFilter_66675072303489_kernel(
    const float* __restrict__ x,
    const float* __restrict__ sigma,
    float* __restrict__ out)
{
    // Planar quartet planes: m=w0, a=w-1+w+1, b=w-2+w+2, c=w-3+w+3 (38.9 KB)
    __shared__ __align__(16) float qm[PR][TW];
    __shared__ __align__(16) float qa[PR][TW];
    __shared__ __align__(16) float qb[PR][TW];
    __shared__ __align__(16) float qc[PR][TW];

    const int ch = blockIdx.z;
    const int x0 = blockIdx.x * TW;
    const int y0 = blockIdx.y * TH;

    const float* xc = x     + (size_t)ch * IMG * IMG;
    const float* sc = sigma + (size_t)ch * IMG * IMG;
    float*       oc = out   + (size_t)ch * IMG * IMG;

    const int tx  = threadIdx.x;
    const int ty  = threadIdx.y;
    const int tid = ty * 32 + tx;

    const int c2  = tx << 1;                 // column 0..62
    const int ly0 = ty << 2;                 // output row 0..28

    // Preload all 4 sigma pairs (latency hides under pass-1)
    const float* sp = sc + (y0 + ly0) * IMG + x0 + c2;
    u64 sg[4];
    sg[0] = *(const u64*)(sp);
    sg[1] = *(const u64*)(sp + IMG);
    sg[2] = *(const u64*)(sp + 2 * IMG);
    sg[3] = *(const u64*)(sp + 3 * IMG);

    // ---- Pass 1: 4-wide strips; interior loads = 3 aligned LDG.128 ----
    // Strip (r, c0) covers plane cols c0..c0+3; x window needed: c0-3..c0+6.
    // Load v[0..11] = x[x0+c0-4 .. x0+c0+7] (16B-aligned base), w[i] = v[i+1].
    const bool interior = (blockIdx.x != 0) & (blockIdx.x != 3) &
                          (blockIdx.y != 0) & (blockIdx.y != 7);
    #pragma unroll
    for (int it = 0; it < 3; it++) {
        int idx = tid + it * 256;
        if (idx < PR * 16) {                 // 38 rows x 16 strips = 608
            int r  = idx >> 4;
            int c0 = (idx & 15) << 2;
            float v[12];
            if (interior) {
                const float4* src =
                    (const float4*)(xc + (y0 + r - 3) * IMG + (x0 + c0 - 4));
                float4 f0 = src[0], f1 = src[1], f2 = src[2];
                v[0]=f0.x; v[1]=f0.y; v[2]=f0.z;  v[3]=f0.w;
                v[4]=f1.x; v[5]=f1.y; v[6]=f1.z;  v[7]=f1.w;
                v[8]=f2.x; v[9]=f2.y; v[10]=f2.z; v[11]=f2.w;
            } else {
                const float* srow = xc + reflect(y0 + r - 3) * IMG;
                #pragma unroll
                for (int j = 0; j < 12; j++)
                    v[j] = srow[reflect(x0 + c0 - 4 + j)];
            }
            // plane col c0+i: m=v[i+4], a=v[i+3]+v[i+5], b=v[i+2]+v[i+6], c=v[i+1]+v[i+7]
            *(float4*)&qm[r][c0] = make_float4(v[4], v[5], v[6], v[7]);
            *(float4*)&qa[r][c0] = make_float4(v[3]+v[5], v[4]+v[6], v[5]+v[7], v[6]+v[8]);
            *(float4*)&qb[r][c0] = make_float4(v[2]+v[6], v[3]+v[7], v[4]+v[8], v[5]+v[9]);
            *(float4*)&qc[r][c0] = make_float4(v[1]+v[7], v[2]+v[8], v[3]+v[9], v[4]+v[10]);
        }
    }

    // ---- Exp chains for all 4 output rows BEFORE the barrier (MUFU hidden) ----
    const u64 NHL = pk2(-0.72134752f, -0.72134752f);   // -0.5*log2(e)
    u64 t[4], t4[4], t9[4];
    #pragma unroll
    for (int k = 0; k < 4; k++) {
        u64 z = f2mul(sg[k], sg[k]);
        z = f2mul(z, NHL);
        float zl, zh; upk2(zl, zh, z);
        t[k]  = pk2(ex2f(zl), ex2f(zh));
        u64 t2 = f2mul(t[k], t[k]);
        t4[k] = f2mul(t2, t2);
        t9[k] = f2mul(f2mul(t4[k], t4[k]), t[k]);
    }
    __syncthreads();

    // ---- Pass 2: stream 10 window rows; 4 packed accumulators ----
    u64 acc[4];
    #pragma unroll
    for (int w = -3; w <= 6; w++) {
        const int prow = ly0 + w + 3;        // 0..37
        const u64 qm_ = *(const u64*)&qm[prow][c2];
        const u64 qa_ = *(const u64*)&qa[prow][c2];
        const u64 qb_ = *(const u64*)&qb[prow][c2];
        const u64 qc_ = *(const u64*)&qc[prow][c2];
        #pragma unroll
        for (int k = 0; k < 4; k++) {
            const int d = (w > k) ? (w - k) : (k - w);
            if (d > 3) continue;
            u64 h = f2fma(t[k],  qa_, qm_);
            h     = f2fma(t4[k], qb_, h);
            h     = f2fma(t9[k], qc_, h);
            if (w == k - 3)     acc[k] = f2mul(t9[k], h);     // first contribution
            else if (d == 3)    acc[k] = f2fma(t9[k], h, acc[k]);
            else if (d == 2)    acc[k] = f2fma(t4[k], h, acc[k]);
            else if (d == 1)    acc[k] = f2fma(t[k],  h, acc[k]);
            else                acc[k] = f2add(acc[k], h);
        }
    }

    // ---- Epilogue: normalize and store ----
    const u64 TWO2 = pk2(2.0f, 2.0f);
    const u64 ONE2 = pk2(1.0f, 1.0f);
    float* op = oc + (y0 + ly0) * IMG + x0 + c2;
    #pragma unroll
    for (int k = 0; k < 4; k++) {
        u64 S  = f2fma(TWO2, f2add(f2add(t[k], t4[k]), t9[k]), ONE2);
        u64 SS = f2mul(S, S);
        float sl, sh; upk2(sl, sh, SS);
        float al, ah; upk2(al, ah, acc[k]);
        *(u64*)(op + k * IMG) = pk2(al * rcpf(sl), ah * rcpf(sh));
    }
}

extern "C" void kernel_launch(void* const* d_in, const int* in_sizes, int n_in,
                              void* d_out, int out_size)
{
    const float* x     = (const float*)d_in[0];
    const float* sigma = (const float*)d_in[1];
    float*       out   = (float*)d_out;

    dim3 block(32, 8, 1);
    dim3 grid(IMG / TW, IMG / TH, 16 * 3);   // 4 x 8 x 48 = 1536
    AdaptiveGaussianFilter_66675072303489_kernel<<<grid, block>>>(x, sigma, out);
}

// round 14
// speedup vs baseline: 1.1045x; 1.0093x over previous
#include <cuda_runtime.h>

#define IMG 256
#define TW 64
#define TH 32
#define PR (TH + 6)   // 38 quartet-plane rows

typedef unsigned long long u64;

// ---- packed f32x2 helpers (sm_103a FFMA2 path, PTX-only) ----
__device__ __forceinline__ u64 pk2(float lo, float hi) {
    u64 r; asm("mov.b64 %0, {%1,%2};" : "=l"(r) : "f"(lo), "f"(hi)); return r;
}
__device__ __forceinline__ void upk2(float& lo, float& hi, u64 p) {
    asm("mov.b64 {%0,%1}, %2;" : "=f"(lo), "=f"(hi) : "l"(p));
}
__device__ __forceinline__ u64 f2fma(u64 a, u64 b, u64 c) {
    u64 d; asm("fma.rn.f32x2 %0,%1,%2,%3;" : "=l"(d) : "l"(a), "l"(b), "l"(c)); return d;
}
__device__ __forceinline__ u64 f2mul(u64 a, u64 b) {
    u64 d; asm("mul.rn.f32x2 %0,%1,%2;" : "=l"(d) : "l"(a), "l"(b)); return d;
}
__device__ __forceinline__ u64 f2add(u64 a, u64 b) {
    u64 d; asm("add.rn.f32x2 %0,%1,%2;" : "=l"(d) : "l"(a), "l"(b)); return d;
}
__device__ __forceinline__ float ex2f(float x) {
    float r; asm("ex2.approx.f32 %0, %1;" : "=f"(r) : "f"(x)); return r;
}
__device__ __forceinline__ float rcpf(float x) {
    float r; asm("rcp.approx.f32 %0, %1;" : "=f"(r) : "f"(x)); return r;
}

__device__ __forceinline__ int reflect(int v) {
    v = (v < 0) ? -v : v;
    return (v > IMG - 1) ? 2 * (IMG - 1) - v : v;
}

__global__ __launch_bounds__(256, 5)
void AdaptiveGaussianFilter_66675072303489_kernel(
    const float* __restrict__ x,
    const float* __restrict__ sigma,
    float* __restrict__ out)
{
    // Planar quartet planes: m=w0, a=w-1+w+1, b=w-2+w+2, c=w-3+w+3 (38.9 KB)
    __shared__ __align__(16) float qm[PR][TW];
    __shared__ __align__(16) float qa[PR][TW];
    __shared__ __align__(16) float qb[PR][TW];
    __shared__ __align__(16) float qc[PR][TW];

    const int ch = blockIdx.z;
    const int x0 = blockIdx.x * TW;
    const int y0 = blockIdx.y * TH;

    const float* xc = x     + (size_t)ch * IMG * IMG;
    const float* sc = sigma + (size_t)ch * IMG * IMG;
    float*       oc = out   + (size_t)ch * IMG * IMG;

    const int tx  = threadIdx.x;
    const int ty  = threadIdx.y;
    const int tid = ty * 32 + tx;

    const int c2  = tx << 1;                 // column 0..62
    const int ly0 = ty << 2;                 // output row 0..28

    // Preload all 4 sigma pairs (latency hides under pass-1)
    const float* sp = sc + (y0 + ly0) * IMG + x0 + c2;
    u64 sg[4];
    sg[0] = *(const u64*)(sp);
    sg[1] = *(const u64*)(sp + IMG);
    sg[2] = *(const u64*)(sp + 2 * IMG);
    sg[3] = *(const u64*)(sp + 3 * IMG);

    // ---- Pass 1: 4-wide strips; interior loads = 3 aligned LDG.128 ----
    // Strip (r, c0) covers plane cols c0..c0+3; x window needed: c0-3..c0+6.
    // Load v[0..11] = x[x0+c0-4 .. x0+c0+7] (16B-aligned base).
    const bool interior = (blockIdx.x != 0) & (blockIdx.x != 3) &
                          (blockIdx.y != 0) & (blockIdx.y != 7);
    #pragma unroll
    for (int it = 0; it < 3; it++) {
        int idx = tid + it * 256;
        if (idx < PR * 16) {                 // 38 rows x 16 strips = 608
            int r  = idx >> 4;
            int c0 = (idx & 15) << 2;
            float v[12];
            if (interior) {
                const float4* src =
                    (const float4*)(xc + (y0 + r - 3) * IMG + (x0 + c0 - 4));
                float4 f0 = src[0], f1 = src[1], f2 = src[2];
                v[0]=f0.x; v[1]=f0.y; v[2]=f0.z;  v[3]=f0.w;
                v[4]=f1.x; v[5]=f1.y; v[6]=f1.z;  v[7]=f1.w;
                v[8]=f2.x; v[9]=f2.y; v[10]=f2.z; v[11]=f2.w;
            } else {
                const float* srow = xc + reflect(y0 + r - 3) * IMG;
                #pragma unroll
                for (int j = 0; j < 12; j++)
                    v[j] = srow[reflect(x0 + c0 - 4 + j)];
            }
            // plane col c0+i: m=v[i+4], a=v[i+3]+v[i+5], b=v[i+2]+v[i+6], c=v[i+1]+v[i+7]
            *(float4*)&qm[r][c0] = make_float4(v[4], v[5], v[6], v[7]);
            *(float4*)&qa[r][c0] = make_float4(v[3]+v[5], v[4]+v[6], v[5]+v[7], v[6]+v[8]);
            *(float4*)&qb[r][c0] = make_float4(v[2]+v[6], v[3]+v[7], v[4]+v[8], v[5]+v[9]);
            *(float4*)&qc[r][c0] = make_float4(v[1]+v[7], v[2]+v[8], v[3]+v[9], v[4]+v[10]);
        }
    }

    // ---- Exp chains for all 4 output rows BEFORE the barrier (MUFU hidden) ----
    const u64 NHL = pk2(-0.72134752f, -0.72134752f);   // -0.5*log2(e)
    u64 t[4], t4[4], t9[4];
    #pragma unroll
    for (int k = 0; k < 4; k++) {
        u64 z = f2mul(sg[k], sg[k]);
        z = f2mul(z, NHL);
        float zl, zh; upk2(zl, zh, z);
        t[k]  = pk2(ex2f(zl), ex2f(zh));
        u64 t2 = f2mul(t[k], t[k]);
        t4[k] = f2mul(t2, t2);
        t9[k] = f2mul(f2mul(t4[k], t4[k]), t[k]);
    }
    __syncthreads();

    // ---- Pass 2: stream 10 window rows; 4 packed accumulators ----
    u64 acc[4];
    #pragma unroll
    for (int w = -3; w <= 6; w++) {
        const int prow = ly0 + w + 3;        // 0..37
        const u64 qm_ = *(const u64*)&qm[prow][c2];
        const u64 qa_ = *(const u64*)&qa[prow][c2];
        const u64 qb_ = *(const u64*)&qb[prow][c2];
        const u64 qc_ = *(const u64*)&qc[prow][c2];
        #pragma unroll
        for (int k = 0; k < 4; k++) {
            const int d = (w > k) ? (w - k) : (k - w);
            if (d > 3) continue;
            u64 h = f2fma(t[k],  qa_, qm_);
            h     = f2fma(t4[k], qb_, h);
            h     = f2fma(t9[k], qc_, h);
            if (w == k - 3)     acc[k] = f2mul(t9[k], h);     // first contribution
            else if (d == 3)    acc[k] = f2fma(t9[k], h, acc[k]);
            else if (d == 2)    acc[k] = f2fma(t4[k], h, acc[k]);
            else if (d == 1)    acc[k] = f2fma(t[k],  h, acc[k]);
            else                acc[k] = f2add(acc[k], h);
        }
    }

    // ---- Epilogue: normalize and store ----
    const u64 TWO2 = pk2(2.0f, 2.0f);
    const u64 ONE2 = pk2(1.0f, 1.0f);
    float* op = oc + (y0 + ly0) * IMG + x0 + c2;
    #pragma unroll
    for (int k = 0; k < 4; k++) {
        u64 S  = f2fma(TWO2, f2add(f2add(t[k], t4[k]), t9[k]), ONE2);
        u64 SS = f2mul(S, S);
        float sl, sh; upk2(sl, sh, SS);
        float al, ah; upk2(al, ah, acc[k]);
        *(u64*)(op + k * IMG) = pk2(al * rcpf(sl), ah * rcpf(sh));
    }
}

extern "C" void kernel_launch(void* const* d_in, const int* in_sizes, int n_in,
                              void* d_out, int out_size)
{
    const float* x     = (const float*)d_in[0];
    const float* sigma = (const float*)d_in[1];
    float*       out   = (float*)d_out;

    dim3 block(32, 8, 1);
    dim3 grid(IMG / TW, IMG / TH, 16 * 3);   // 4 x 8 x 48 = 1536
    AdaptiveGaussianFilter_66675072303489_kernel<<<grid, block>>>(x, sigma, out);
}